// round 6
// baseline (speedup 1.0000x reference)
#include <cuda_runtime.h>
#include <stdint.h>

#define BB 16
#define TT 400
#define UPP 512
#define NCH 9                 // H+1
#define NROWS (BB*NCH)        // 144
#define TPRIME (TT*UPP)       // 204800
#define TOTAL (BB*TPRIME)     // 3276800

// per-(row, frame) fractional part of the EXACT exclusive phase prefix (in cycles)
__device__ float g_frac[NROWS*TT];

// ---------------------------------------------------------------------------
// Kernel 1: exact (f64) exclusive per-frame phase prefixes, frac'd to f32.
// One warp per row (b,ch); 13 contiguous frames per lane + f64 warp scan.
// ---------------------------------------------------------------------------
__global__ void prep_kernel(const float* __restrict__ f0) {
    int warp = threadIdx.x >> 5;
    int lane = threadIdx.x & 31;
    int row = blockIdx.x * 4 + warp;
    if (row >= NROWS) return;
    int b = row / NCH, c = row % NCH;
    float kmul = (float)(c + 1);   // ch 0: base; ch 1..8: base*(c+1)
    const float INV_SR = 2.5e-5f;  // RN(1/40000)

    int t0 = lane * 13;
    int t1 = t0 + 13; if (t1 > TT) t1 = TT;
    if (t0 > TT) t0 = TT;

    // pass 1: chunk totals
    double csum = 0.0;
    for (int t = t0; t < t1; ++t) {
        float base = __fmul_rn(f0[b*TT + t], INV_SR);
        float r = (c == 0) ? base : __fmul_rn(base, kmul);
        csum += (double)r * 512.0;
    }
    // inclusive warp scan (f64), then make exclusive
    double pre = csum;
    #pragma unroll
    for (int d = 1; d < 32; d <<= 1) {
        double v = __shfl_up_sync(0xffffffffu, pre, d);
        if (lane >= d) pre += v;
    }
    pre -= csum;

    // pass 2: per-frame exclusive prefixes -> frac -> f32
    double run = pre;
    for (int t = t0; t < t1; ++t) {
        float base = __fmul_rn(f0[b*TT + t], INV_SR);
        float r = (c == 0) ? base : __fmul_rn(base, kmul);
        g_frac[row*TT + t] = (float)(run - trunc(run));
        run += (double)r * 512.0;
    }
}

// ---------------------------------------------------------------------------
// Kernel 2: one block per frame (b,t), thread j = sample in frame.
// Exact phase via 2-prod + exact per-frame fractional prefix. (PASSES: 8.0e-4)
// ---------------------------------------------------------------------------
__global__ void main_kernel(const float* __restrict__ f0,
                            const float* __restrict__ w,
                            const float* __restrict__ bias,
                            float* __restrict__ out, int parts) {
    int f = blockIdx.x;            // b*TT + t
    int b = f / TT, t = f % TT;
    int j = threadIdx.x;

    __shared__ float sh_r[NCH], sh_f[NCH], sh_w[NCH];
    __shared__ float sh_b, sh_uv;
    if (j < NCH) {
        float base = __fmul_rn(f0[b*TT + t], 2.5e-5f);
        sh_r[j] = (j == 0) ? base : __fmul_rn(base, (float)(j + 1));
        sh_f[j] = g_frac[(b*NCH + j)*TT + t];
        sh_w[j] = w[j];
    } else if (j == NCH) {
        sh_b = bias[0];
    } else if (j == NCH + 1) {
        sh_uv = (f0[b*TT + t] > 0.0f) ? 1.0f : 0.0f;
    }
    __syncthreads();

    const float TWO_PI = 6.2831853071795864769f;   // f32 0x40C90FDB
    float fm = (float)(j + 1);
    float uvv = sh_uv;
    float dot = 0.0f;

    #pragma unroll
    for (int c = 0; c < NCH; ++c) {
        float r = sh_r[c];
        float p_hi = __fmul_rn(fm, r);
        float p_lo = __fmaf_rn(fm, r, -p_hi);          // exact low part
        float fp   = __fsub_rn(p_hi, truncf(p_hi));    // exact frac of hi
        float v    = __fadd_rn(__fadd_rn(fp, p_lo), sh_f[c]);
        v = __fsub_rn(v, truncf(v));
        float ph = __fmul_rn(v, TWO_PI);
        float sine = __fmul_rn(__fmul_rn(0.1f, sinf(ph)), uvv);
        dot = fmaf(sine, sh_w[c], dot);
    }
    float merged = tanhf(__fadd_rn(dot, sh_b));

    int idx = f*UPP + j;
    out[idx] = merged;
    if (parts >= 2) out[TOTAL + idx] = uvv;
}

// ---------------------------------------------------------------------------
// Kernel 3: JAX threefry2x32 noise, PARTITIONABLE mode (modern default):
// per element i: counter pair = (hi32(i), lo32(i)) = (0, i), key (0,1),
// bits = x0_out ^ x1_out.  Then uniform[nextafter(-1,0),1) -> sqrt(2)*erfinv
// -> * 0.003.
// ---------------------------------------------------------------------------
__device__ __forceinline__ float bits_to_noise(uint32_t bits) {
    float fb = __uint_as_float((bits >> 9) | 0x3f800000u) - 1.0f;   // [0,1)
    const float LO = __uint_as_float(0xBF7FFFFFu);                  // nextafter(-1,0)
    float u = fmaxf(LO, __fadd_rn(__fmul_rn(fb, 2.0f), LO));        // (hi-lo) rounds to 2.0f
    float ww = -log1pf(-u * u);
    float p;
    if (ww < 5.0f) {
        ww -= 2.5f;
        p = 2.81022636e-08f;
        p = fmaf(p, ww, 3.43273939e-07f);
        p = fmaf(p, ww, -3.5233877e-06f);
        p = fmaf(p, ww, -4.39150654e-06f);
        p = fmaf(p, ww, 0.00021858087f);
        p = fmaf(p, ww, -0.00125372503f);
        p = fmaf(p, ww, -0.00417768164f);
        p = fmaf(p, ww, 0.246640727f);
        p = fmaf(p, ww, 1.50140941f);
    } else {
        ww = sqrtf(ww) - 3.0f;
        p = -0.000200214257f;
        p = fmaf(p, ww, 0.000100950558f);
        p = fmaf(p, ww, 0.00134934322f);
        p = fmaf(p, ww, -0.00367342844f);
        p = fmaf(p, ww, 0.00573950773f);
        p = fmaf(p, ww, -0.0076224613f);
        p = fmaf(p, ww, 0.00943887047f);
        p = fmaf(p, ww, 1.00167406f);
        p = fmaf(p, ww, 2.83297682f);
    }
    float z = p * u;                                   // erf_inv
    return 0.003f * (__uint_as_float(0x3FB504F3u) * z); // * sqrt(2)f32 * NOISE_STD
}

__global__ void noise_kernel(float* __restrict__ out) {
    int i = blockIdx.x * blockDim.x + threadIdx.x;
    if (i >= TOTAL) return;

    const uint32_t ks0 = 0u, ks1 = 1u, ks2 = 0x1BD11BDBu;  // 0x1BD11BDA^0^1
    uint32_t x0 = 0u + ks0;               // counts_hi + ks0
    uint32_t x1 = (uint32_t)i + ks1;      // counts_lo + ks1

#define TF_ROUND(r) { x0 += x1; x1 = ((x1 << (r)) | (x1 >> (32 - (r)))); x1 ^= x0; }
    TF_ROUND(13) TF_ROUND(15) TF_ROUND(26) TF_ROUND(6)
    x0 += ks1; x1 += ks2 + 1u;
    TF_ROUND(17) TF_ROUND(29) TF_ROUND(16) TF_ROUND(24)
    x0 += ks2; x1 += ks0 + 2u;
    TF_ROUND(13) TF_ROUND(15) TF_ROUND(26) TF_ROUND(6)
    x0 += ks0; x1 += ks1 + 3u;
    TF_ROUND(17) TF_ROUND(29) TF_ROUND(16) TF_ROUND(24)
    x0 += ks1; x1 += ks2 + 4u;
    TF_ROUND(13) TF_ROUND(15) TF_ROUND(26) TF_ROUND(6)
    x0 += ks2; x1 += ks0 + 5u;
#undef TF_ROUND

    out[2*TOTAL + i] = bits_to_noise(x0 ^ x1);   // partitionable 32-bit combine
}

// ---------------------------------------------------------------------------
extern "C" void kernel_launch(void* const* d_in, const int* in_sizes, int n_in,
                              void* d_out, int out_size) {
    const float* f0 = (const float*)d_in[0];
    const float* w  = (const float*)d_in[1];
    const float* b  = (const float*)d_in[2];
    float* out = (float*)d_out;
    int parts = out_size / TOTAL;   // 1: sine_merge, 2: +uv, 3: +noise

    prep_kernel<<<(NROWS + 3) / 4, 128>>>(f0);
    main_kernel<<<BB * TT, UPP>>>(f0, w, b, out, parts);
    if (parts >= 3)
        noise_kernel<<<(TOTAL + 255) / 256, 256>>>(out);
}

// round 7
// speedup vs baseline: 1.4383x; 1.4383x over previous
#include <cuda_runtime.h>
#include <stdint.h>

#define BB 16
#define TT 400
#define UPP 512
#define NCH 9                 // H+1
#define NROWS (BB*NCH)        // 144
#define TPRIME (TT*UPP)       // 204800
#define TOTAL (BB*TPRIME)     // 3276800

// per-(row, frame) fractional part of the EXACT exclusive phase prefix (cycles)
__device__ float g_frac[NROWS*TT];

// ---------------------------------------------------------------------------
// Kernel 1: exact exclusive per-frame phase prefixes via int64 fixed point.
// 1 warp per row (b,ch). Frame increment r*512 cycles is represented EXACTLY
// in units of 2^-33 cycles: r = mant*2^(E-150) -> r*512*2^33 = mant<<(E-108).
// (f0 in [100,400] Hz => r >= 2.5e-3 => E >= 118, shift >= 10; sums < 2^48.)
// frac = (prefix & (2^33-1)) * 2^-33, single rounding to f32 (same as before).
// ---------------------------------------------------------------------------
__global__ void prep_kernel(const float* __restrict__ f0) {
    int row = blockIdx.x;          // 144 blocks of 32 threads
    int lane = threadIdx.x;
    int b = row / NCH, c = row % NCH;
    float kmul = (float)(c + 1);
    const float INV_SR = 2.5e-5f;  // RN(1/40000)

    int t0 = lane * 13;
    int t1 = t0 + 13; if (t1 > TT) t1 = TT;
    if (t0 > TT) t0 = TT;

    long long k[13];
    long long csum = 0;
    #pragma unroll
    for (int u = 0; u < 13; ++u) {
        long long kk = 0;
        int t = t0 + u;
        if (t < t1) {
            float base = __fmul_rn(f0[b*TT + t], INV_SR);
            float r = (c == 0) ? base : __fmul_rn(base, kmul);
            uint32_t ub = __float_as_uint(r);
            int E = (int)((ub >> 23) & 0xFF);
            long long mant = (long long)((ub & 0x7FFFFFu) | 0x800000u);
            int sh = E - 108;                       // r*512*2^33 = mant << sh
            kk = (sh >= 0) ? (mant << sh) : (mant >> (-sh));
        }
        k[u] = kk;
        csum += kk;
    }

    // inclusive warp scan (int64) -> exclusive
    long long pre = csum;
    #pragma unroll
    for (int d = 1; d < 32; d <<= 1) {
        long long v = __shfl_up_sync(0xffffffffu, pre, d);
        if (lane >= d) pre += v;
    }
    pre -= csum;

    const long long MASK33 = (1ll << 33) - 1;
    const float SCALE = 1.1641532182693481e-10f;    // 2^-33
    long long run = pre;
    #pragma unroll
    for (int u = 0; u < 13; ++u) {
        int t = t0 + u;
        if (t < t1)
            g_frac[row*TT + t] = (float)(run & MASK33) * SCALE;
        run += k[u];
    }
}

// ---------------------------------------------------------------------------
// Kernel 2 (fused): one block per frame, thread j = sample. Exact phase via
// 2-prod + exact prefix frac; __sinf (MUFU) sines; fast tanh via __expf;
// threefry-partitionable noise fused in (noise flat index == out index).
// ---------------------------------------------------------------------------
__device__ __forceinline__ float bits_to_noise(uint32_t bits) {
    float fb = __uint_as_float((bits >> 9) | 0x3f800000u) - 1.0f;   // [0,1)
    const float LO = __uint_as_float(0xBF7FFFFFu);                  // nextafter(-1,0)
    float u = fmaxf(LO, __fadd_rn(__fmul_rn(fb, 2.0f), LO));
    float ww = -log1pf(-u * u);
    float p;
    if (ww < 5.0f) {
        ww -= 2.5f;
        p = 2.81022636e-08f;
        p = fmaf(p, ww, 3.43273939e-07f);
        p = fmaf(p, ww, -3.5233877e-06f);
        p = fmaf(p, ww, -4.39150654e-06f);
        p = fmaf(p, ww, 0.00021858087f);
        p = fmaf(p, ww, -0.00125372503f);
        p = fmaf(p, ww, -0.00417768164f);
        p = fmaf(p, ww, 0.246640727f);
        p = fmaf(p, ww, 1.50140941f);
    } else {
        ww = sqrtf(ww) - 3.0f;
        p = -0.000200214257f;
        p = fmaf(p, ww, 0.000100950558f);
        p = fmaf(p, ww, 0.00134934322f);
        p = fmaf(p, ww, -0.00367342844f);
        p = fmaf(p, ww, 0.00573950773f);
        p = fmaf(p, ww, -0.0076224613f);
        p = fmaf(p, ww, 0.00943887047f);
        p = fmaf(p, ww, 1.00167406f);
        p = fmaf(p, ww, 2.83297682f);
    }
    float z = p * u;                                    // erf_inv
    return 0.003f * (__uint_as_float(0x3FB504F3u) * z); // * sqrt(2)f32 * 0.003
}

__global__ void fused_kernel(const float* __restrict__ f0,
                             const float* __restrict__ w,
                             const float* __restrict__ bias,
                             float* __restrict__ out, int parts) {
    int f = blockIdx.x;            // b*TT + t
    int b = f / TT, t = f % TT;
    int j = threadIdx.x;

    __shared__ float sh_r[NCH], sh_f[NCH], sh_w[NCH];
    __shared__ float sh_b, sh_uv;
    if (j < NCH) {
        float base = __fmul_rn(f0[b*TT + t], 2.5e-5f);
        sh_r[j] = (j == 0) ? base : __fmul_rn(base, (float)(j + 1));
        sh_f[j] = g_frac[(b*NCH + j)*TT + t];
        sh_w[j] = w[j];
    } else if (j == NCH) {
        sh_b = bias[0];
    } else if (j == NCH + 1) {
        sh_uv = (f0[b*TT + t] > 0.0f) ? 1.0f : 0.0f;
    }
    __syncthreads();

    const float TWO_PI = 6.2831853071795864769f;
    float fm = (float)(j + 1);
    float dot = 0.0f;

    #pragma unroll
    for (int c = 0; c < NCH; ++c) {
        float r = sh_r[c];
        float p_hi = __fmul_rn(fm, r);
        float p_lo = __fmaf_rn(fm, r, -p_hi);          // exact low part (33-bit prod)
        float fp   = __fsub_rn(p_hi, truncf(p_hi));    // exact frac of hi
        float v    = __fadd_rn(__fadd_rn(fp, p_lo), sh_f[c]);
        v = __fsub_rn(v, truncf(v));                   // [0,1) up to eps
        float s = __sinf(__fmul_rn(v, TWO_PI));        // MUFU.SIN, abs err ~4e-7
        dot = __fmaf_rn(s, sh_w[c], dot);
    }
    float uvv = sh_uv;
    float x = __fmaf_rn(dot, 0.1f * uvv, sh_b);        // = 0.1*uv*sum(sin*w) + b
    // tanh via exp: mathematically exact identity, err ~1e-6 abs
    float ex = __expf(__fmul_rn(2.0f, x));
    float merged = 1.0f - __fdividef(2.0f, ex + 1.0f);

    int idx = f*UPP + j;
    out[idx] = merged;
    if (parts >= 2) out[TOTAL + idx] = uvv;

    if (parts >= 3) {
        // threefry2x32 partitionable: counter (0, idx), key (0,1), out = x0^x1
        const uint32_t ks0 = 0u, ks1 = 1u, ks2 = 0x1BD11BDBu;
        uint32_t x0 = 0u + ks0;
        uint32_t x1 = (uint32_t)idx + ks1;
#define TF_ROUND(r) { x0 += x1; x1 = ((x1 << (r)) | (x1 >> (32 - (r)))); x1 ^= x0; }
        TF_ROUND(13) TF_ROUND(15) TF_ROUND(26) TF_ROUND(6)
        x0 += ks1; x1 += ks2 + 1u;
        TF_ROUND(17) TF_ROUND(29) TF_ROUND(16) TF_ROUND(24)
        x0 += ks2; x1 += ks0 + 2u;
        TF_ROUND(13) TF_ROUND(15) TF_ROUND(26) TF_ROUND(6)
        x0 += ks0; x1 += ks1 + 3u;
        TF_ROUND(17) TF_ROUND(29) TF_ROUND(16) TF_ROUND(24)
        x0 += ks1; x1 += ks2 + 4u;
        TF_ROUND(13) TF_ROUND(15) TF_ROUND(26) TF_ROUND(6)
        x0 += ks2; x1 += ks0 + 5u;
#undef TF_ROUND
        out[2*TOTAL + idx] = bits_to_noise(x0 ^ x1);
    }
}

// ---------------------------------------------------------------------------
extern "C" void kernel_launch(void* const* d_in, const int* in_sizes, int n_in,
                              void* d_out, int out_size) {
    const float* f0 = (const float*)d_in[0];
    const float* w  = (const float*)d_in[1];
    const float* b  = (const float*)d_in[2];
    float* out = (float*)d_out;
    int parts = out_size / TOTAL;   // 1: sine_merge, 2: +uv, 3: +noise

    prep_kernel<<<NROWS, 32>>>(f0);
    fused_kernel<<<BB * TT, UPP>>>(f0, w, b, out, parts);
}

// round 8
// speedup vs baseline: 1.6324x; 1.1349x over previous
#include <cuda_runtime.h>
#include <stdint.h>

#define BB 16
#define TT 400
#define UPP 512
#define NCH 9                 // H+1
#define NROWS (BB*NCH)        // 144
#define TPRIME (TT*UPP)       // 204800
#define TOTAL (BB*TPRIME)     // 3276800

// per-(row, frame) fractional part of the EXACT exclusive phase prefix (cycles)
__device__ float g_frac[NROWS*TT];

// ---------------------------------------------------------------------------
// Kernel 1: exact exclusive per-frame phase prefixes via int64 fixed point.
// 1 warp per row (b,ch). r*512 cycles is EXACT in units of 2^-33 cycles.
// ---------------------------------------------------------------------------
__global__ void prep_kernel(const float* __restrict__ f0) {
    int row = blockIdx.x;          // 144 blocks of 32 threads
    int lane = threadIdx.x;
    int b = row / NCH, c = row % NCH;
    float kmul = (float)(c + 1);
    const float INV_SR = 2.5e-5f;  // RN(1/40000)

    int t0 = lane * 13;
    int t1 = t0 + 13; if (t1 > TT) t1 = TT;
    if (t0 > TT) t0 = TT;

    long long k[13];
    long long csum = 0;
    #pragma unroll
    for (int u = 0; u < 13; ++u) {
        long long kk = 0;
        int t = t0 + u;
        if (t < t1) {
            float base = __fmul_rn(f0[b*TT + t], INV_SR);
            float r = (c == 0) ? base : __fmul_rn(base, kmul);
            uint32_t ub = __float_as_uint(r);
            int E = (int)((ub >> 23) & 0xFF);
            long long mant = (long long)((ub & 0x7FFFFFu) | 0x800000u);
            int sh = E - 108;                       // r*512*2^33 = mant << sh
            kk = (sh >= 0) ? (mant << sh) : (mant >> (-sh));
        }
        k[u] = kk;
        csum += kk;
    }

    // inclusive warp scan (int64) -> exclusive
    long long pre = csum;
    #pragma unroll
    for (int d = 1; d < 32; d <<= 1) {
        long long v = __shfl_up_sync(0xffffffffu, pre, d);
        if (lane >= d) pre += v;
    }
    pre -= csum;

    const long long MASK33 = (1ll << 33) - 1;
    const float SCALE = 1.1641532182693481e-10f;    // 2^-33
    long long run = pre;
    #pragma unroll
    for (int u = 0; u < 13; ++u) {
        int t = t0 + u;
        if (t < t1)
            g_frac[row*TT + t] = (float)(run & MASK33) * SCALE;
        run += k[u];
    }
}

// ---------------------------------------------------------------------------
// Kernel 2 (fused): grid (TT, BB), one block per frame, thread j = sample.
// Exact phase via 2-prod + exact prefix frac; __sinf; fast tanh; fused
// partitionable-threefry noise. Instruction-count-lean variant.
// ---------------------------------------------------------------------------
__device__ __forceinline__ float bits_to_noise(uint32_t bits) {
    float fb = __uint_as_float((bits >> 9) | 0x3f800000u) - 1.0f;   // [0,1)
    const float LO = __uint_as_float(0xBF7FFFFFu);                  // nextafter(-1,0)
    float u = fmaxf(LO, __fadd_rn(__fmul_rn(fb, 2.0f), LO));
    // -log(1-u^2): fma keeps accuracy at the |u|->1 tail; MUFU.LG2 fast log
    float ww = -__logf(__fmaf_rn(-u, u, 1.0f));
    float p;
    if (ww < 5.0f) {
        ww -= 2.5f;
        p = 2.81022636e-08f;
        p = fmaf(p, ww, 3.43273939e-07f);
        p = fmaf(p, ww, -3.5233877e-06f);
        p = fmaf(p, ww, -4.39150654e-06f);
        p = fmaf(p, ww, 0.00021858087f);
        p = fmaf(p, ww, -0.00125372503f);
        p = fmaf(p, ww, -0.00417768164f);
        p = fmaf(p, ww, 0.246640727f);
        p = fmaf(p, ww, 1.50140941f);
    } else {
        ww = sqrtf(ww) - 3.0f;
        p = -0.000200214257f;
        p = fmaf(p, ww, 0.000100950558f);
        p = fmaf(p, ww, 0.00134934322f);
        p = fmaf(p, ww, -0.00367342844f);
        p = fmaf(p, ww, 0.00573950773f);
        p = fmaf(p, ww, -0.0076224613f);
        p = fmaf(p, ww, 0.00943887047f);
        p = fmaf(p, ww, 1.00167406f);
        p = fmaf(p, ww, 2.83297682f);
    }
    float z = p * u;                                    // erf_inv
    return 0.003f * (__uint_as_float(0x3FB504F3u) * z); // * sqrt(2)f32 * 0.003
}

__global__ void __launch_bounds__(UPP) fused_kernel(
        const float* __restrict__ f0,
        const float* __restrict__ w,
        const float* __restrict__ bias,
        float* __restrict__ out, int parts) {
    int t = blockIdx.x, b = blockIdx.y;
    int f = b * TT + t;            // == f0 flat index
    int j = threadIdx.x;

    __shared__ float sh_r[NCH], sh_f[NCH], sh_w[NCH];
    __shared__ float sh_b, sh_uv;
    if (j < NCH) {
        float base = __fmul_rn(f0[f], 2.5e-5f);
        sh_r[j] = (j == 0) ? base : __fmul_rn(base, (float)(j + 1));
        sh_f[j] = g_frac[(b*NCH + j)*TT + t];
        sh_w[j] = w[j];
    } else if (j == NCH) {
        sh_b = bias[0];
    } else if (j == NCH + 1) {
        sh_uv = (f0[f] > 0.0f) ? 1.0f : 0.0f;
    }
    __syncthreads();

    const float TWO_PI = 6.2831853071795864769f;
    float fm = (float)(j + 1);
    float dot = 0.0f;

    #pragma unroll
    for (int c = 0; c < NCH; ++c) {
        float r = sh_r[c];
        float p_hi = __fmul_rn(fm, r);
        float p_lo = __fmaf_rn(fm, r, -p_hi);          // exact low part (33-bit prod)
        float fp   = __fsub_rn(p_hi, truncf(p_hi));    // exact frac of hi, [0,1)
        float v    = __fadd_rn(__fadd_rn(fp, p_lo), sh_f[c]);  // (-eps, 2)
        float s = __sinf(__fmul_rn(v, TWO_PI));        // arg <= 4pi: MUFU fine
        dot = __fmaf_rn(s, sh_w[c], dot);
    }
    float uvv = sh_uv;
    float x = __fmaf_rn(dot, 0.1f * uvv, sh_b);        // 0.1*uv*sum + b
    float ex = __expf(__fmul_rn(2.0f, x));
    float merged = 1.0f - __fdividef(2.0f, ex + 1.0f); // tanh(x)

    int idx = f*UPP + j;
    out[idx] = merged;
    if (parts >= 2) out[TOTAL + idx] = uvv;

    if (parts >= 3) {
        // threefry2x32 partitionable: counter (0, idx), key (0,1), out = x0^x1
        const uint32_t ks0 = 0u, ks1 = 1u, ks2 = 0x1BD11BDBu;
        uint32_t x0 = 0u + ks0;
        uint32_t x1 = (uint32_t)idx + ks1;
#define TF_ROUND(r) { x0 += x1; x1 = ((x1 << (r)) | (x1 >> (32 - (r)))); x1 ^= x0; }
        TF_ROUND(13) TF_ROUND(15) TF_ROUND(26) TF_ROUND(6)
        x0 += ks1; x1 += ks2 + 1u;
        TF_ROUND(17) TF_ROUND(29) TF_ROUND(16) TF_ROUND(24)
        x0 += ks2; x1 += ks0 + 2u;
        TF_ROUND(13) TF_ROUND(15) TF_ROUND(26) TF_ROUND(6)
        x0 += ks0; x1 += ks1 + 3u;
        TF_ROUND(17) TF_ROUND(29) TF_ROUND(16) TF_ROUND(24)
        x0 += ks1; x1 += ks2 + 4u;
        TF_ROUND(13) TF_ROUND(15) TF_ROUND(26) TF_ROUND(6)
        x0 += ks2; x1 += ks0 + 5u;
#undef TF_ROUND
        out[2*TOTAL + idx] = bits_to_noise(x0 ^ x1);
    }
}

// ---------------------------------------------------------------------------
extern "C" void kernel_launch(void* const* d_in, const int* in_sizes, int n_in,
                              void* d_out, int out_size) {
    const float* f0 = (const float*)d_in[0];
    const float* w  = (const float*)d_in[1];
    const float* b  = (const float*)d_in[2];
    float* out = (float*)d_out;
    int parts = out_size / TOTAL;   // 1: sine_merge, 2: +uv, 3: +noise

    prep_kernel<<<NROWS, 32>>>(f0);
    fused_kernel<<<dim3(TT, BB), UPP>>>(f0, w, b, out, parts);
}

// round 9
// speedup vs baseline: 1.6590x; 1.0163x over previous
#include <cuda_runtime.h>
#include <stdint.h>

#define BB 16
#define TT 400
#define UPP 512
#define NCH 9                 // H+1
#define NROWS (BB*NCH)        // 144
#define TPRIME (TT*UPP)       // 204800
#define TOTAL (BB*TPRIME)     // 3276800

// per-(row, frame) fractional part of the EXACT exclusive phase prefix (cycles)
__device__ float g_frac[NROWS*TT];

// ---------------------------------------------------------------------------
// Kernel 1: exact exclusive per-frame phase prefixes via int64 fixed point.
// 1 warp per row (b,ch). r*512 cycles is EXACT in units of 2^-33 cycles.
// ---------------------------------------------------------------------------
__global__ void prep_kernel(const float* __restrict__ f0) {
    int row = blockIdx.x;          // 144 blocks of 32 threads
    int lane = threadIdx.x;
    int b = row / NCH, c = row % NCH;
    float kmul = (float)(c + 1);
    const float INV_SR = 2.5e-5f;  // RN(1/40000)

    int t0 = lane * 13;
    int t1 = t0 + 13; if (t1 > TT) t1 = TT;
    if (t0 > TT) t0 = TT;

    long long k[13];
    long long csum = 0;
    #pragma unroll
    for (int u = 0; u < 13; ++u) {
        long long kk = 0;
        int t = t0 + u;
        if (t < t1) {
            float base = __fmul_rn(f0[b*TT + t], INV_SR);
            float r = (c == 0) ? base : __fmul_rn(base, kmul);
            uint32_t ub = __float_as_uint(r);
            int E = (int)((ub >> 23) & 0xFF);
            long long mant = (long long)((ub & 0x7FFFFFu) | 0x800000u);
            int sh = E - 108;                       // r*512*2^33 = mant << sh
            kk = (sh >= 0) ? (mant << sh) : (mant >> (-sh));
        }
        k[u] = kk;
        csum += kk;
    }

    // inclusive warp scan (int64) -> exclusive
    long long pre = csum;
    #pragma unroll
    for (int d = 1; d < 32; d <<= 1) {
        long long v = __shfl_up_sync(0xffffffffu, pre, d);
        if (lane >= d) pre += v;
    }
    pre -= csum;

    const long long MASK33 = (1ll << 33) - 1;
    const float SCALE = 1.1641532182693481e-10f;    // 2^-33
    long long run = pre;
    #pragma unroll
    for (int u = 0; u < 13; ++u) {
        int t = t0 + u;
        if (t < t1)
            g_frac[row*TT + t] = (float)(run & MASK33) * SCALE;
        run += k[u];
    }
}

// ---------------------------------------------------------------------------
// Kernel 2 (fused): grid (TT, BB), one block per frame, thread j = sample.
// Per-channel constants packed as float4 {r, frac, w, -} -> one LDS.128.
// Phase: v = fma(m, r, frac); v -= trunc(v)   (err <= ulp(m*r) ~ 4e-6 cyc)
// __sinf sines, fast tanh, fused partitionable-threefry noise.
// ---------------------------------------------------------------------------
__device__ __forceinline__ float bits_to_noise(uint32_t bits) {
    float fb = __uint_as_float((bits >> 9) | 0x3f800000u) - 1.0f;   // [0,1)
    const float LO = __uint_as_float(0xBF7FFFFFu);                  // nextafter(-1,0)
    float u = fmaxf(LO, __fadd_rn(__fmul_rn(fb, 2.0f), LO));
    float ww = -__logf(__fmaf_rn(-u, u, 1.0f));     // -log(1-u^2), MUFU.LG2
    float p;
    if (ww < 5.0f) {
        ww -= 2.5f;
        p = 2.81022636e-08f;
        p = fmaf(p, ww, 3.43273939e-07f);
        p = fmaf(p, ww, -3.5233877e-06f);
        p = fmaf(p, ww, -4.39150654e-06f);
        p = fmaf(p, ww, 0.00021858087f);
        p = fmaf(p, ww, -0.00125372503f);
        p = fmaf(p, ww, -0.00417768164f);
        p = fmaf(p, ww, 0.246640727f);
        p = fmaf(p, ww, 1.50140941f);
    } else {
        ww = sqrtf(ww) - 3.0f;
        p = -0.000200214257f;
        p = fmaf(p, ww, 0.000100950558f);
        p = fmaf(p, ww, 0.00134934322f);
        p = fmaf(p, ww, -0.00367342844f);
        p = fmaf(p, ww, 0.00573950773f);
        p = fmaf(p, ww, -0.0076224613f);
        p = fmaf(p, ww, 0.00943887047f);
        p = fmaf(p, ww, 1.00167406f);
        p = fmaf(p, ww, 2.83297682f);
    }
    float z = p * u;                                    // erf_inv
    return 0.003f * (__uint_as_float(0x3FB504F3u) * z); // * sqrt(2)f32 * 0.003
}

__global__ void __launch_bounds__(UPP) fused_kernel(
        const float* __restrict__ f0,
        const float* __restrict__ w,
        const float* __restrict__ bias,
        float* __restrict__ out, int parts) {
    int t = blockIdx.x, b = blockIdx.y;
    int f = b * TT + t;            // == f0 flat index
    int j = threadIdx.x;

    __shared__ float4 sh4[NCH];    // {r, frac, w, pad}
    __shared__ float sh_b, sh_uv;
    if (j < NCH) {
        float base = __fmul_rn(f0[f], 2.5e-5f);
        float r = (j == 0) ? base : __fmul_rn(base, (float)(j + 1));
        sh4[j] = make_float4(r, g_frac[(b*NCH + j)*TT + t], w[j], 0.0f);
    } else if (j == NCH) {
        sh_b = bias[0];
    } else if (j == NCH + 1) {
        sh_uv = (f0[f] > 0.0f) ? 1.0f : 0.0f;
    }
    __syncthreads();

    const float TWO_PI = 6.2831853071795864769f;
    float fm = (float)(j + 1);
    float dot = 0.0f;

    #pragma unroll
    for (int c = 0; c < NCH; ++c) {
        float4 q = sh4[c];                              // 1x LDS.128
        float v = __fmaf_rn(fm, q.x, q.y);              // m*r + frac  (<= ~47)
        v = __fsub_rn(v, truncf(v));                    // exact sub: frac in [0,1)
        float s = __sinf(__fmul_rn(v, TWO_PI));         // MUFU.SIN
        dot = __fmaf_rn(s, q.z, dot);
    }
    float uvv = sh_uv;
    float x = __fmaf_rn(dot, 0.1f * uvv, sh_b);         // 0.1*uv*sum + b
    float ex = __expf(__fmul_rn(2.0f, x));
    float merged = 1.0f - __fdividef(2.0f, ex + 1.0f);  // tanh(x)

    int idx = f*UPP + j;
    out[idx] = merged;
    if (parts >= 2) out[TOTAL + idx] = uvv;

    if (parts >= 3) {
        // threefry2x32 partitionable: counter (0, idx), key (0,1), out = x0^x1
        const uint32_t ks0 = 0u, ks1 = 1u, ks2 = 0x1BD11BDBu;
        uint32_t x0 = 0u + ks0;
        uint32_t x1 = (uint32_t)idx + ks1;
#define TF_ROUND(r) { x0 += x1; x1 = ((x1 << (r)) | (x1 >> (32 - (r)))); x1 ^= x0; }
        TF_ROUND(13) TF_ROUND(15) TF_ROUND(26) TF_ROUND(6)
        x0 += ks1; x1 += ks2 + 1u;
        TF_ROUND(17) TF_ROUND(29) TF_ROUND(16) TF_ROUND(24)
        x0 += ks2; x1 += ks0 + 2u;
        TF_ROUND(13) TF_ROUND(15) TF_ROUND(26) TF_ROUND(6)
        x0 += ks0; x1 += ks1 + 3u;
        TF_ROUND(17) TF_ROUND(29) TF_ROUND(16) TF_ROUND(24)
        x0 += ks1; x1 += ks2 + 4u;
        TF_ROUND(13) TF_ROUND(15) TF_ROUND(26) TF_ROUND(6)
        x0 += ks2; x1 += ks0 + 5u;
#undef TF_ROUND
        out[2*TOTAL + idx] = bits_to_noise(x0 ^ x1);
    }
}

// ---------------------------------------------------------------------------
extern "C" void kernel_launch(void* const* d_in, const int* in_sizes, int n_in,
                              void* d_out, int out_size) {
    const float* f0 = (const float*)d_in[0];
    const float* w  = (const float*)d_in[1];
    const float* b  = (const float*)d_in[2];
    float* out = (float*)d_out;
    int parts = out_size / TOTAL;   // 1: sine_merge, 2: +uv, 3: +noise

    prep_kernel<<<NROWS, 32>>>(f0);
    fused_kernel<<<dim3(TT, BB), UPP>>>(f0, w, b, out, parts);
}

// round 10
// speedup vs baseline: 1.7410x; 1.0495x over previous
#include <cuda_runtime.h>
#include <stdint.h>

#define BB 16
#define TT 400
#define UPP 512
#define NCH 9                 // H+1
#define NROWS (BB*NCH)        // 144
#define TPRIME (TT*UPP)       // 204800
#define TOTAL (BB*TPRIME)     // 3276800

// per-(row, frame) fractional part of the EXACT exclusive phase prefix (cycles)
__device__ float g_frac[NROWS*TT];

// ---------------------------------------------------------------------------
// Kernel 1: exact exclusive per-frame phase prefixes via int64 fixed point.
// 1 warp per row (b,ch). r*512 cycles is EXACT in units of 2^-33 cycles.
// ---------------------------------------------------------------------------
__global__ void prep_kernel(const float* __restrict__ f0) {
    int row = blockIdx.x;          // 144 blocks of 32 threads
    int lane = threadIdx.x;
    int b = row / NCH, c = row % NCH;
    float kmul = (float)(c + 1);
    const float INV_SR = 2.5e-5f;  // RN(1/40000)

    int t0 = lane * 13;
    int t1 = t0 + 13; if (t1 > TT) t1 = TT;
    if (t0 > TT) t0 = TT;

    long long k[13];
    long long csum = 0;
    #pragma unroll
    for (int u = 0; u < 13; ++u) {
        long long kk = 0;
        int t = t0 + u;
        if (t < t1) {
            float base = __fmul_rn(f0[b*TT + t], INV_SR);
            float r = (c == 0) ? base : __fmul_rn(base, kmul);
            uint32_t ub = __float_as_uint(r);
            int E = (int)((ub >> 23) & 0xFF);
            long long mant = (long long)((ub & 0x7FFFFFu) | 0x800000u);
            int sh = E - 108;                       // r*512*2^33 = mant << sh
            kk = (sh >= 0) ? (mant << sh) : (mant >> (-sh));
        }
        k[u] = kk;
        csum += kk;
    }

    // inclusive warp scan (int64) -> exclusive
    long long pre = csum;
    #pragma unroll
    for (int d = 1; d < 32; d <<= 1) {
        long long v = __shfl_up_sync(0xffffffffu, pre, d);
        if (lane >= d) pre += v;
    }
    pre -= csum;

    const long long MASK33 = (1ll << 33) - 1;
    const float SCALE = 1.1641532182693481e-10f;    // 2^-33
    long long run = pre;
    #pragma unroll
    for (int u = 0; u < 13; ++u) {
        int t = t0 + u;
        if (t < t1)
            g_frac[row*TT + t] = (float)(run & MASK33) * SCALE;
        run += k[u];
    }
}

// ---------------------------------------------------------------------------
// Kernel 2 (fused): grid (TT, BB), one block per frame, thread j = sample.
// Per-channel (r, frac) as float2 (LDS.64) + scalar w (LDS.32): lean live
// set for occupancy. Phase: v = fma(m, r, frac); v -= trunc(v).
// __sinf sines, fast tanh, fused partitionable-threefry noise.
// __launch_bounds__(512,4) caps regs at 32 -> 100% theoretical occupancy.
// ---------------------------------------------------------------------------
__device__ __forceinline__ float bits_to_noise(uint32_t bits) {
    float fb = __uint_as_float((bits >> 9) | 0x3f800000u) - 1.0f;   // [0,1)
    const float LO = __uint_as_float(0xBF7FFFFFu);                  // nextafter(-1,0)
    float u = fmaxf(LO, __fadd_rn(__fmul_rn(fb, 2.0f), LO));
    float ww = -__logf(__fmaf_rn(-u, u, 1.0f));     // -log(1-u^2), MUFU.LG2
    float p;
    if (ww < 5.0f) {
        ww -= 2.5f;
        p = 2.81022636e-08f;
        p = fmaf(p, ww, 3.43273939e-07f);
        p = fmaf(p, ww, -3.5233877e-06f);
        p = fmaf(p, ww, -4.39150654e-06f);
        p = fmaf(p, ww, 0.00021858087f);
        p = fmaf(p, ww, -0.00125372503f);
        p = fmaf(p, ww, -0.00417768164f);
        p = fmaf(p, ww, 0.246640727f);
        p = fmaf(p, ww, 1.50140941f);
    } else {
        ww = sqrtf(ww) - 3.0f;
        p = -0.000200214257f;
        p = fmaf(p, ww, 0.000100950558f);
        p = fmaf(p, ww, 0.00134934322f);
        p = fmaf(p, ww, -0.00367342844f);
        p = fmaf(p, ww, 0.00573950773f);
        p = fmaf(p, ww, -0.0076224613f);
        p = fmaf(p, ww, 0.00943887047f);
        p = fmaf(p, ww, 1.00167406f);
        p = fmaf(p, ww, 2.83297682f);
    }
    float z = p * u;                                    // erf_inv
    return 0.003f * (__uint_as_float(0x3FB504F3u) * z); // * sqrt(2)f32 * 0.003
}

__global__ void __launch_bounds__(UPP, 4) fused_kernel(
        const float* __restrict__ f0,
        const float* __restrict__ w,
        const float* __restrict__ bias,
        float* __restrict__ out, int parts) {
    int t = blockIdx.x, b = blockIdx.y;
    int f = b * TT + t;            // == f0 flat index
    int j = threadIdx.x;

    __shared__ float2 sh_rf[NCH];  // {r, frac}
    __shared__ float sh_w[NCH];
    __shared__ float sh_b, sh_uv;
    if (j < NCH) {
        float base = __fmul_rn(f0[f], 2.5e-5f);
        float r = (j == 0) ? base : __fmul_rn(base, (float)(j + 1));
        sh_rf[j] = make_float2(r, g_frac[(b*NCH + j)*TT + t]);
        sh_w[j] = w[j];
    } else if (j == NCH) {
        sh_b = bias[0];
    } else if (j == NCH + 1) {
        sh_uv = (f0[f] > 0.0f) ? 1.0f : 0.0f;
    }
    __syncthreads();

    const float TWO_PI = 6.2831853071795864769f;
    float fm = (float)(j + 1);
    float dot = 0.0f;

    #pragma unroll
    for (int c = 0; c < NCH; ++c) {
        float2 q = sh_rf[c];                            // LDS.64 broadcast
        float v = __fmaf_rn(fm, q.x, q.y);              // m*r + frac  (<= ~47)
        v = __fsub_rn(v, truncf(v));                    // exact sub: frac in [0,1)
        float s = __sinf(__fmul_rn(v, TWO_PI));         // MUFU.SIN
        dot = __fmaf_rn(s, sh_w[c], dot);
    }
    float uvv = sh_uv;
    float x = __fmaf_rn(dot, 0.1f * uvv, sh_b);         // 0.1*uv*sum + b
    float ex = __expf(__fmul_rn(2.0f, x));
    float merged = 1.0f - __fdividef(2.0f, ex + 1.0f);  // tanh(x)

    int idx = f*UPP + j;
    out[idx] = merged;
    if (parts >= 2) out[TOTAL + idx] = uvv;

    if (parts >= 3) {
        // threefry2x32 partitionable: counter (0, idx), key (0,1), out = x0^x1
        const uint32_t ks0 = 0u, ks1 = 1u, ks2 = 0x1BD11BDBu;
        uint32_t x0 = 0u + ks0;
        uint32_t x1 = (uint32_t)idx + ks1;
#define TF_ROUND(r) { x0 += x1; x1 = ((x1 << (r)) | (x1 >> (32 - (r)))); x1 ^= x0; }
        TF_ROUND(13) TF_ROUND(15) TF_ROUND(26) TF_ROUND(6)
        x0 += ks1; x1 += ks2 + 1u;
        TF_ROUND(17) TF_ROUND(29) TF_ROUND(16) TF_ROUND(24)
        x0 += ks2; x1 += ks0 + 2u;
        TF_ROUND(13) TF_ROUND(15) TF_ROUND(26) TF_ROUND(6)
        x0 += ks0; x1 += ks1 + 3u;
        TF_ROUND(17) TF_ROUND(29) TF_ROUND(16) TF_ROUND(24)
        x0 += ks1; x1 += ks2 + 4u;
        TF_ROUND(13) TF_ROUND(15) TF_ROUND(26) TF_ROUND(6)
        x0 += ks2; x1 += ks0 + 5u;
#undef TF_ROUND
        out[2*TOTAL + idx] = bits_to_noise(x0 ^ x1);
    }
}

// ---------------------------------------------------------------------------
extern "C" void kernel_launch(void* const* d_in, const int* in_sizes, int n_in,
                              void* d_out, int out_size) {
    const float* f0 = (const float*)d_in[0];
    const float* w  = (const float*)d_in[1];
    const float* b  = (const float*)d_in[2];
    float* out = (float*)d_out;
    int parts = out_size / TOTAL;   // 1: sine_merge, 2: +uv, 3: +noise

    prep_kernel<<<NROWS, 32>>>(f0);
    fused_kernel<<<dim3(TT, BB), UPP>>>(f0, w, b, out, parts);
}

// round 11
// speedup vs baseline: 2.1043x; 1.2087x over previous
#include <cuda_runtime.h>
#include <stdint.h>

#define BB 16
#define TT 400
#define UPP 512
#define NCH 9                 // H+1
#define NROWS (BB*NCH)        // 144
#define TPRIME (TT*UPP)       // 204800
#define TOTAL (BB*TPRIME)     // 3276800

// per-(row, frame) fractional part of the EXACT exclusive phase prefix (cycles)
__device__ float g_frac[NROWS*TT];

// ---------------------------------------------------------------------------
// Kernel 1: exact exclusive per-frame phase prefixes via int64 fixed point.
// 1 warp per row (b,ch). r*512 cycles is EXACT in units of 2^-33 cycles.
// ---------------------------------------------------------------------------
__global__ void prep_kernel(const float* __restrict__ f0) {
    int row = blockIdx.x;          // 144 blocks of 32 threads
    int lane = threadIdx.x;
    int b = row / NCH, c = row % NCH;
    float kmul = (float)(c + 1);
    const float INV_SR = 2.5e-5f;  // RN(1/40000)

    int t0 = lane * 13;
    int t1 = t0 + 13; if (t1 > TT) t1 = TT;
    if (t0 > TT) t0 = TT;

    long long k[13];
    long long csum = 0;
    #pragma unroll
    for (int u = 0; u < 13; ++u) {
        long long kk = 0;
        int t = t0 + u;
        if (t < t1) {
            float base = __fmul_rn(f0[b*TT + t], INV_SR);
            float r = (c == 0) ? base : __fmul_rn(base, kmul);
            uint32_t ub = __float_as_uint(r);
            int E = (int)((ub >> 23) & 0xFF);
            long long mant = (long long)((ub & 0x7FFFFFu) | 0x800000u);
            int sh = E - 108;                       // r*512*2^33 = mant << sh
            kk = (sh >= 0) ? (mant << sh) : (mant >> (-sh));
        }
        k[u] = kk;
        csum += kk;
    }

    // inclusive warp scan (int64) -> exclusive
    long long pre = csum;
    #pragma unroll
    for (int d = 1; d < 32; d <<= 1) {
        long long v = __shfl_up_sync(0xffffffffu, pre, d);
        if (lane >= d) pre += v;
    }
    pre -= csum;

    const long long MASK33 = (1ll << 33) - 1;
    const float SCALE = 1.1641532182693481e-10f;    // 2^-33
    long long run = pre;
    #pragma unroll
    for (int u = 0; u < 13; ++u) {
        int t = t0 + u;
        if (t < t1)
            g_frac[row*TT + t] = (float)(run & MASK33) * SCALE;
        run += k[u];
    }
}

// ---------------------------------------------------------------------------
// Kernel 2 (fused): grid (TT, BB), 128 threads/block, 4 samples per thread.
// LDS + prologue amortized 4x; float4 stores; MUFU.TANH; __sinf sines;
// fused partitionable-threefry noise.
// ---------------------------------------------------------------------------
__device__ __forceinline__ float bits_to_noise(uint32_t bits) {
    float fb = __uint_as_float((bits >> 9) | 0x3f800000u) - 1.0f;   // [0,1)
    const float LO = __uint_as_float(0xBF7FFFFFu);                  // nextafter(-1,0)
    float u = fmaxf(LO, __fadd_rn(__fmul_rn(fb, 2.0f), LO));
    float ww = -__logf(__fmaf_rn(-u, u, 1.0f));     // -log(1-u^2), MUFU.LG2
    float p;
    if (ww < 5.0f) {
        ww -= 2.5f;
        p = 2.81022636e-08f;
        p = fmaf(p, ww, 3.43273939e-07f);
        p = fmaf(p, ww, -3.5233877e-06f);
        p = fmaf(p, ww, -4.39150654e-06f);
        p = fmaf(p, ww, 0.00021858087f);
        p = fmaf(p, ww, -0.00125372503f);
        p = fmaf(p, ww, -0.00417768164f);
        p = fmaf(p, ww, 0.246640727f);
        p = fmaf(p, ww, 1.50140941f);
    } else {
        ww = sqrtf(ww) - 3.0f;
        p = -0.000200214257f;
        p = fmaf(p, ww, 0.000100950558f);
        p = fmaf(p, ww, 0.00134934322f);
        p = fmaf(p, ww, -0.00367342844f);
        p = fmaf(p, ww, 0.00573950773f);
        p = fmaf(p, ww, -0.0076224613f);
        p = fmaf(p, ww, 0.00943887047f);
        p = fmaf(p, ww, 1.00167406f);
        p = fmaf(p, ww, 2.83297682f);
    }
    float z = p * u;                                    // erf_inv
    return 0.003f * (__uint_as_float(0x3FB504F3u) * z); // * sqrt(2)f32 * 0.003
}

__device__ __forceinline__ float fast_tanh(float x) {
    float r;
    asm("tanh.approx.f32 %0, %1;" : "=f"(r) : "f"(x));
    return r;
}

__device__ __forceinline__ float threefry_noise(uint32_t idx) {
    const uint32_t ks0 = 0u, ks1 = 1u, ks2 = 0x1BD11BDBu;
    uint32_t x0 = 0u + ks0;
    uint32_t x1 = idx + ks1;
#define TF_ROUND(r) { x0 += x1; x1 = ((x1 << (r)) | (x1 >> (32 - (r)))); x1 ^= x0; }
    TF_ROUND(13) TF_ROUND(15) TF_ROUND(26) TF_ROUND(6)
    x0 += ks1; x1 += ks2 + 1u;
    TF_ROUND(17) TF_ROUND(29) TF_ROUND(16) TF_ROUND(24)
    x0 += ks2; x1 += ks0 + 2u;
    TF_ROUND(13) TF_ROUND(15) TF_ROUND(26) TF_ROUND(6)
    x0 += ks0; x1 += ks1 + 3u;
    TF_ROUND(17) TF_ROUND(29) TF_ROUND(16) TF_ROUND(24)
    x0 += ks1; x1 += ks2 + 4u;
    TF_ROUND(13) TF_ROUND(15) TF_ROUND(26) TF_ROUND(6)
    x0 += ks2; x1 += ks0 + 5u;
#undef TF_ROUND
    return bits_to_noise(x0 ^ x1);
}

__global__ void __launch_bounds__(128, 12) fused_kernel(
        const float* __restrict__ f0,
        const float* __restrict__ w,
        const float* __restrict__ bias,
        float* __restrict__ out, int parts) {
    int t = blockIdx.x, b = blockIdx.y;
    int f = b * TT + t;            // == f0 flat index
    int tid = threadIdx.x;         // 0..127

    __shared__ float2 sh_rf[NCH];  // {r, frac}
    __shared__ float sh_w[NCH];
    __shared__ float sh_b, sh_uv;
    if (tid < NCH) {
        float base = __fmul_rn(f0[f], 2.5e-5f);
        float r = (tid == 0) ? base : __fmul_rn(base, (float)(tid + 1));
        sh_rf[tid] = make_float2(r, g_frac[(b*NCH + tid)*TT + t]);
        sh_w[tid] = w[tid];
    } else if (tid == NCH) {
        sh_b = bias[0];
    } else if (tid == NCH + 1) {
        sh_uv = (f0[f] > 0.0f) ? 1.0f : 0.0f;
    }
    __syncthreads();

    const float TWO_PI = 6.2831853071795864769f;
    int j0 = tid * 4;
    float fm0 = (float)(j0 + 1);
    float d0 = 0.0f, d1 = 0.0f, d2 = 0.0f, d3 = 0.0f;

    #pragma unroll
    for (int c = 0; c < NCH; ++c) {
        float2 q = sh_rf[c];                            // LDS.64 broadcast, x1 per 4 samples
        float wc = sh_w[c];
        float v0 = __fmaf_rn(fm0,        q.x, q.y); v0 = __fsub_rn(v0, truncf(v0));
        float v1 = __fmaf_rn(fm0 + 1.0f, q.x, q.y); v1 = __fsub_rn(v1, truncf(v1));
        float v2 = __fmaf_rn(fm0 + 2.0f, q.x, q.y); v2 = __fsub_rn(v2, truncf(v2));
        float v3 = __fmaf_rn(fm0 + 3.0f, q.x, q.y); v3 = __fsub_rn(v3, truncf(v3));
        d0 = __fmaf_rn(__sinf(__fmul_rn(v0, TWO_PI)), wc, d0);
        d1 = __fmaf_rn(__sinf(__fmul_rn(v1, TWO_PI)), wc, d1);
        d2 = __fmaf_rn(__sinf(__fmul_rn(v2, TWO_PI)), wc, d2);
        d3 = __fmaf_rn(__sinf(__fmul_rn(v3, TWO_PI)), wc, d3);
    }
    float uvv = sh_uv;
    float su = 0.1f * uvv, bb2 = sh_b;
    float4 mg;
    mg.x = fast_tanh(__fmaf_rn(d0, su, bb2));
    mg.y = fast_tanh(__fmaf_rn(d1, su, bb2));
    mg.z = fast_tanh(__fmaf_rn(d2, su, bb2));
    mg.w = fast_tanh(__fmaf_rn(d3, su, bb2));

    int idx = f*UPP + j0;                               // 4-aligned
    *reinterpret_cast<float4*>(out + idx) = mg;
    if (parts >= 2)
        *reinterpret_cast<float4*>(out + TOTAL + idx) = make_float4(uvv, uvv, uvv, uvv);

    if (parts >= 3) {
        float4 nz;
        nz.x = threefry_noise((uint32_t)idx);
        nz.y = threefry_noise((uint32_t)idx + 1u);
        nz.z = threefry_noise((uint32_t)idx + 2u);
        nz.w = threefry_noise((uint32_t)idx + 3u);
        *reinterpret_cast<float4*>(out + 2*TOTAL + idx) = nz;
    }
}

// ---------------------------------------------------------------------------
extern "C" void kernel_launch(void* const* d_in, const int* in_sizes, int n_in,
                              void* d_out, int out_size) {
    const float* f0 = (const float*)d_in[0];
    const float* w  = (const float*)d_in[1];
    const float* b  = (const float*)d_in[2];
    float* out = (float*)d_out;
    int parts = out_size / TOTAL;   // 1: sine_merge, 2: +uv, 3: +noise

    prep_kernel<<<NROWS, 32>>>(f0);
    fused_kernel<<<dim3(TT, BB), 128>>>(f0, w, b, out, parts);
}

// round 12
// speedup vs baseline: 2.3297x; 1.1071x over previous
#include <cuda_runtime.h>
#include <stdint.h>

#define BB 16
#define TT 400
#define UPP 512
#define NCH 9                 // H+1
#define NROWS (BB*NCH)        // 144
#define TPRIME (TT*UPP)       // 204800
#define TOTAL (BB*TPRIME)     // 3276800

// per-(row, frame) fractional part of the EXACT exclusive phase prefix (cycles)
__device__ float g_frac[NROWS*TT];

// ---------------------------------------------------------------------------
// Kernel 1: exact exclusive per-frame phase prefixes via int64 fixed point.
// 1 warp per row (b,ch). r*512 cycles is EXACT in units of 2^-33 cycles.
// ---------------------------------------------------------------------------
__global__ void prep_kernel(const float* __restrict__ f0) {
    int row = blockIdx.x;          // 144 blocks of 32 threads
    int lane = threadIdx.x;
    int b = row / NCH, c = row % NCH;
    float kmul = (float)(c + 1);
    const float INV_SR = 2.5e-5f;  // RN(1/40000)

    int t0 = lane * 13;
    int t1 = t0 + 13; if (t1 > TT) t1 = TT;
    if (t0 > TT) t0 = TT;

    long long k[13];
    long long csum = 0;
    #pragma unroll
    for (int u = 0; u < 13; ++u) {
        long long kk = 0;
        int t = t0 + u;
        if (t < t1) {
            float base = __fmul_rn(f0[b*TT + t], INV_SR);
            float r = (c == 0) ? base : __fmul_rn(base, kmul);
            uint32_t ub = __float_as_uint(r);
            int E = (int)((ub >> 23) & 0xFF);
            long long mant = (long long)((ub & 0x7FFFFFu) | 0x800000u);
            int sh = E - 108;                       // r*512*2^33 = mant << sh
            kk = (sh >= 0) ? (mant << sh) : (mant >> (-sh));
        }
        k[u] = kk;
        csum += kk;
    }

    // inclusive warp scan (int64) -> exclusive
    long long pre = csum;
    #pragma unroll
    for (int d = 1; d < 32; d <<= 1) {
        long long v = __shfl_up_sync(0xffffffffu, pre, d);
        if (lane >= d) pre += v;
    }
    pre -= csum;

    const long long MASK33 = (1ll << 33) - 1;
    const float SCALE = 1.1641532182693481e-10f;    // 2^-33
    long long run = pre;
    #pragma unroll
    for (int u = 0; u < 13; ++u) {
        int t = t0 + u;
        if (t < t1)
            g_frac[row*TT + t] = (float)(run & MASK33) * SCALE;
        run += k[u];
    }
}

// ---------------------------------------------------------------------------
// Kernel 2 (fused): grid (TT, BB), 128 threads/block, 4 samples per thread.
// Phase pre-scaled to radians in shared: v = fma(m, r2pi, f2pi); __sinf(v)
// relies on MUFU's internal range reduction (v <= ~300 rad, phase err ~5e-5
// rad, negligible). 0.1*uv folded into shared weights. MUFU.TANH merge.
// Fused partitionable-threefry noise, float4 stores.
// ---------------------------------------------------------------------------
__device__ __forceinline__ float bits_to_noise(uint32_t bits) {
    float fb = __uint_as_float((bits >> 9) | 0x3f800000u) - 1.0f;   // [0,1)
    const float LO = __uint_as_float(0xBF7FFFFFu);                  // nextafter(-1,0)
    float u = fmaxf(LO, __fadd_rn(__fmul_rn(fb, 2.0f), LO));
    float ww = -__logf(__fmaf_rn(-u, u, 1.0f));     // -log(1-u^2), MUFU.LG2
    float p;
    if (ww < 5.0f) {
        ww -= 2.5f;
        p = 2.81022636e-08f;
        p = fmaf(p, ww, 3.43273939e-07f);
        p = fmaf(p, ww, -3.5233877e-06f);
        p = fmaf(p, ww, -4.39150654e-06f);
        p = fmaf(p, ww, 0.00021858087f);
        p = fmaf(p, ww, -0.00125372503f);
        p = fmaf(p, ww, -0.00417768164f);
        p = fmaf(p, ww, 0.246640727f);
        p = fmaf(p, ww, 1.50140941f);
    } else {
        ww = sqrtf(ww) - 3.0f;
        p = -0.000200214257f;
        p = fmaf(p, ww, 0.000100950558f);
        p = fmaf(p, ww, 0.00134934322f);
        p = fmaf(p, ww, -0.00367342844f);
        p = fmaf(p, ww, 0.00573950773f);
        p = fmaf(p, ww, -0.0076224613f);
        p = fmaf(p, ww, 0.00943887047f);
        p = fmaf(p, ww, 1.00167406f);
        p = fmaf(p, ww, 2.83297682f);
    }
    float z = p * u;                                    // erf_inv
    return 0.003f * (__uint_as_float(0x3FB504F3u) * z); // * sqrt(2)f32 * 0.003
}

__device__ __forceinline__ float fast_tanh(float x) {
    float r;
    asm("tanh.approx.f32 %0, %1;" : "=f"(r) : "f"(x));
    return r;
}

__device__ __forceinline__ float threefry_noise(uint32_t idx) {
    const uint32_t ks0 = 0u, ks1 = 1u, ks2 = 0x1BD11BDBu;
    uint32_t x0 = 0u + ks0;
    uint32_t x1 = idx + ks1;
#define TF_ROUND(r) { x0 += x1; x1 = ((x1 << (r)) | (x1 >> (32 - (r)))); x1 ^= x0; }
    TF_ROUND(13) TF_ROUND(15) TF_ROUND(26) TF_ROUND(6)
    x0 += ks1; x1 += ks2 + 1u;
    TF_ROUND(17) TF_ROUND(29) TF_ROUND(16) TF_ROUND(24)
    x0 += ks2; x1 += ks0 + 2u;
    TF_ROUND(13) TF_ROUND(15) TF_ROUND(26) TF_ROUND(6)
    x0 += ks0; x1 += ks1 + 3u;
    TF_ROUND(17) TF_ROUND(29) TF_ROUND(16) TF_ROUND(24)
    x0 += ks1; x1 += ks2 + 4u;
    TF_ROUND(13) TF_ROUND(15) TF_ROUND(26) TF_ROUND(6)
    x0 += ks2; x1 += ks0 + 5u;
#undef TF_ROUND
    return bits_to_noise(x0 ^ x1);
}

__global__ void __launch_bounds__(128, 12) fused_kernel(
        const float* __restrict__ f0,
        const float* __restrict__ w,
        const float* __restrict__ bias,
        float* __restrict__ out, int parts) {
    int t = blockIdx.x, b = blockIdx.y;
    int f = b * TT + t;            // == f0 flat index
    int tid = threadIdx.x;         // 0..127

    __shared__ float2 sh_rf[NCH];  // {r*2pi, frac*2pi}  (radians)
    __shared__ float sh_wm[NCH];   // 0.1*uv*w[c]
    __shared__ float sh_b;
    __shared__ float sh_uv;
    if (tid < NCH) {
        const float TWO_PI = 6.2831853071795864769f;
        float base = __fmul_rn(f0[f], 2.5e-5f);
        float r = (tid == 0) ? base : __fmul_rn(base, (float)(tid + 1));
        float uvv = (f0[f] > 0.0f) ? 1.0f : 0.0f;
        sh_rf[tid] = make_float2(r * TWO_PI,
                                 g_frac[(b*NCH + tid)*TT + t] * TWO_PI);
        sh_wm[tid] = 0.1f * uvv * w[tid];
        if (tid == 0) { sh_b = bias[0]; sh_uv = uvv; }
    }
    __syncthreads();

    int j0 = tid * 4;
    float fm0 = (float)(j0 + 1);
    float d0 = 0.0f, d1 = 0.0f, d2 = 0.0f, d3 = 0.0f;

    #pragma unroll
    for (int c = 0; c < NCH; ++c) {
        float2 q = sh_rf[c];                            // LDS.64 broadcast
        float wc = sh_wm[c];
        d0 = __fmaf_rn(__sinf(__fmaf_rn(fm0,        q.x, q.y)), wc, d0);
        d1 = __fmaf_rn(__sinf(__fmaf_rn(fm0 + 1.0f, q.x, q.y)), wc, d1);
        d2 = __fmaf_rn(__sinf(__fmaf_rn(fm0 + 2.0f, q.x, q.y)), wc, d2);
        d3 = __fmaf_rn(__sinf(__fmaf_rn(fm0 + 3.0f, q.x, q.y)), wc, d3);
    }
    float bb2 = sh_b;
    float uvv = sh_uv;
    float4 mg;
    mg.x = fast_tanh(__fadd_rn(d0, bb2));
    mg.y = fast_tanh(__fadd_rn(d1, bb2));
    mg.z = fast_tanh(__fadd_rn(d2, bb2));
    mg.w = fast_tanh(__fadd_rn(d3, bb2));

    int idx = f*UPP + j0;                               // 4-aligned
    *reinterpret_cast<float4*>(out + idx) = mg;
    if (parts >= 2)
        *reinterpret_cast<float4*>(out + TOTAL + idx) = make_float4(uvv, uvv, uvv, uvv);

    if (parts >= 3) {
        float4 nz;
        nz.x = threefry_noise((uint32_t)idx);
        nz.y = threefry_noise((uint32_t)idx + 1u);
        nz.z = threefry_noise((uint32_t)idx + 2u);
        nz.w = threefry_noise((uint32_t)idx + 3u);
        *reinterpret_cast<float4*>(out + 2*TOTAL + idx) = nz;
    }
}

// ---------------------------------------------------------------------------
extern "C" void kernel_launch(void* const* d_in, const int* in_sizes, int n_in,
                              void* d_out, int out_size) {
    const float* f0 = (const float*)d_in[0];
    const float* w  = (const float*)d_in[1];
    const float* b  = (const float*)d_in[2];
    float* out = (float*)d_out;
    int parts = out_size / TOTAL;   // 1: sine_merge, 2: +uv, 3: +noise

    prep_kernel<<<NROWS, 32>>>(f0);
    fused_kernel<<<dim3(TT, BB), 128>>>(f0, w, b, out, parts);
}

// round 13
// speedup vs baseline: 2.4444x; 1.0492x over previous
#include <cuda_runtime.h>
#include <stdint.h>

#define BB 16
#define TT 400
#define UPP 512
#define NCH 9                 // H+1
#define NROWS (BB*NCH)        // 144
#define TPRIME (TT*UPP)       // 204800
#define TOTAL (BB*TPRIME)     // 3276800

// per-(row, frame) fractional part of the EXACT exclusive phase prefix (cycles)
__device__ float g_frac[NROWS*TT];

// ---------------------------------------------------------------------------
// Kernel 1: exact exclusive per-frame phase prefixes via int64 fixed point.
// 1 warp per row (b,ch). r*512 cycles is EXACT in units of 2^-33 cycles.
// ---------------------------------------------------------------------------
__global__ void prep_kernel(const float* __restrict__ f0) {
    int row = blockIdx.x;          // 144 blocks of 32 threads
    int lane = threadIdx.x;
    int b = row / NCH, c = row % NCH;
    float kmul = (float)(c + 1);
    const float INV_SR = 2.5e-5f;  // RN(1/40000)

    int t0 = lane * 13;
    int t1 = t0 + 13; if (t1 > TT) t1 = TT;
    if (t0 > TT) t0 = TT;

    long long k[13];
    long long csum = 0;
    #pragma unroll
    for (int u = 0; u < 13; ++u) {
        long long kk = 0;
        int t = t0 + u;
        if (t < t1) {
            float base = __fmul_rn(f0[b*TT + t], INV_SR);
            float r = (c == 0) ? base : __fmul_rn(base, kmul);
            uint32_t ub = __float_as_uint(r);
            int E = (int)((ub >> 23) & 0xFF);
            long long mant = (long long)((ub & 0x7FFFFFu) | 0x800000u);
            int sh = E - 108;                       // r*512*2^33 = mant << sh
            kk = (sh >= 0) ? (mant << sh) : (mant >> (-sh));
        }
        k[u] = kk;
        csum += kk;
    }

    // inclusive warp scan (int64) -> exclusive
    long long pre = csum;
    #pragma unroll
    for (int d = 1; d < 32; d <<= 1) {
        long long v = __shfl_up_sync(0xffffffffu, pre, d);
        if (lane >= d) pre += v;
    }
    pre -= csum;

    const long long MASK33 = (1ll << 33) - 1;
    const float SCALE = 1.1641532182693481e-10f;    // 2^-33
    long long run = pre;
    #pragma unroll
    for (int u = 0; u < 13; ++u) {
        int t = t0 + u;
        if (t < t1)
            g_frac[row*TT + t] = (float)(run & MASK33) * SCALE;
        run += k[u];
    }
}

// ---------------------------------------------------------------------------
// Kernel 2 (fused): grid (TT, BB), 128 threads/block, 4 samples per thread.
// Radian-prescaled phase constants in shared; MUFU sin/tanh; fused
// partitionable-threefry noise; float4 stores.
// __launch_bounds__(128,16) -> 32 regs -> 100% theoretical occupancy.
// ---------------------------------------------------------------------------
__device__ __forceinline__ float bits_to_noise(uint32_t bits) {
    float fb = __uint_as_float((bits >> 9) | 0x3f800000u) - 1.0f;   // [0,1)
    const float LO = __uint_as_float(0xBF7FFFFFu);                  // nextafter(-1,0)
    float u = fmaxf(LO, __fadd_rn(__fmul_rn(fb, 2.0f), LO));
    float ww = -__logf(__fmaf_rn(-u, u, 1.0f));     // -log(1-u^2), MUFU.LG2
    float p;
    if (ww < 5.0f) {
        ww -= 2.5f;
        p = 2.81022636e-08f;
        p = fmaf(p, ww, 3.43273939e-07f);
        p = fmaf(p, ww, -3.5233877e-06f);
        p = fmaf(p, ww, -4.39150654e-06f);
        p = fmaf(p, ww, 0.00021858087f);
        p = fmaf(p, ww, -0.00125372503f);
        p = fmaf(p, ww, -0.00417768164f);
        p = fmaf(p, ww, 0.246640727f);
        p = fmaf(p, ww, 1.50140941f);
    } else {
        ww = sqrtf(ww) - 3.0f;
        p = -0.000200214257f;
        p = fmaf(p, ww, 0.000100950558f);
        p = fmaf(p, ww, 0.00134934322f);
        p = fmaf(p, ww, -0.00367342844f);
        p = fmaf(p, ww, 0.00573950773f);
        p = fmaf(p, ww, -0.0076224613f);
        p = fmaf(p, ww, 0.00943887047f);
        p = fmaf(p, ww, 1.00167406f);
        p = fmaf(p, ww, 2.83297682f);
    }
    // 0.003 * sqrt2_f32 * (p*u), scales folded (<=1 ulp vs reference)
    return 0.0042426409f * (p * u);
}

__device__ __forceinline__ float fast_tanh(float x) {
    float r;
    asm("tanh.approx.f32 %0, %1;" : "=f"(r) : "f"(x));
    return r;
}

__device__ __forceinline__ float threefry_noise(uint32_t idx) {
    const uint32_t ks0 = 0u, ks1 = 1u, ks2 = 0x1BD11BDBu;
    uint32_t x0 = 0u + ks0;
    uint32_t x1 = idx + ks1;
#define TF_ROUND(r) { x0 += x1; x1 = ((x1 << (r)) | (x1 >> (32 - (r)))); x1 ^= x0; }
    TF_ROUND(13) TF_ROUND(15) TF_ROUND(26) TF_ROUND(6)
    x0 += ks1; x1 += ks2 + 1u;
    TF_ROUND(17) TF_ROUND(29) TF_ROUND(16) TF_ROUND(24)
    x0 += ks2; x1 += ks0 + 2u;
    TF_ROUND(13) TF_ROUND(15) TF_ROUND(26) TF_ROUND(6)
    x0 += ks0; x1 += ks1 + 3u;
    TF_ROUND(17) TF_ROUND(29) TF_ROUND(16) TF_ROUND(24)
    x0 += ks1; x1 += ks2 + 4u;
    TF_ROUND(13) TF_ROUND(15) TF_ROUND(26) TF_ROUND(6)
    x0 += ks2; x1 += ks0 + 5u;
#undef TF_ROUND
    return bits_to_noise(x0 ^ x1);
}

__global__ void __launch_bounds__(128, 16) fused_kernel(
        const float* __restrict__ f0,
        const float* __restrict__ w,
        const float* __restrict__ bias,
        float* __restrict__ out, int parts) {
    int t = blockIdx.x, b = blockIdx.y;
    int f = b * TT + t;            // == f0 flat index
    int tid = threadIdx.x;         // 0..127

    __shared__ float2 sh_rf[NCH];  // {r*2pi, frac*2pi}  (radians)
    __shared__ float sh_wm[NCH];   // 0.1*uv*w[c]
    __shared__ float sh_b;
    __shared__ float sh_uv;
    if (tid < NCH) {
        const float TWO_PI = 6.2831853071795864769f;
        float base = __fmul_rn(f0[f], 2.5e-5f);
        float r = (tid == 0) ? base : __fmul_rn(base, (float)(tid + 1));
        float uvv = (f0[f] > 0.0f) ? 1.0f : 0.0f;
        sh_rf[tid] = make_float2(r * TWO_PI,
                                 g_frac[(b*NCH + tid)*TT + t] * TWO_PI);
        sh_wm[tid] = 0.1f * uvv * w[tid];
        if (tid == 0) { sh_b = bias[0]; sh_uv = uvv; }
    }
    __syncthreads();

    int j0 = tid * 4;
    float fm0 = (float)(j0 + 1);
    float d0 = 0.0f, d1 = 0.0f, d2 = 0.0f, d3 = 0.0f;

    #pragma unroll
    for (int c = 0; c < NCH; ++c) {
        float2 q = sh_rf[c];                            // LDS.64 broadcast
        float wc = sh_wm[c];
        d0 = __fmaf_rn(__sinf(__fmaf_rn(fm0,        q.x, q.y)), wc, d0);
        d1 = __fmaf_rn(__sinf(__fmaf_rn(fm0 + 1.0f, q.x, q.y)), wc, d1);
        d2 = __fmaf_rn(__sinf(__fmaf_rn(fm0 + 2.0f, q.x, q.y)), wc, d2);
        d3 = __fmaf_rn(__sinf(__fmaf_rn(fm0 + 3.0f, q.x, q.y)), wc, d3);
    }
    float bb2 = sh_b;
    float uvv = sh_uv;
    float4 mg;
    mg.x = fast_tanh(__fadd_rn(d0, bb2));
    mg.y = fast_tanh(__fadd_rn(d1, bb2));
    mg.z = fast_tanh(__fadd_rn(d2, bb2));
    mg.w = fast_tanh(__fadd_rn(d3, bb2));

    int idx = f*UPP + j0;                               // 4-aligned
    *reinterpret_cast<float4*>(out + idx) = mg;
    if (parts >= 2)
        *reinterpret_cast<float4*>(out + TOTAL + idx) = make_float4(uvv, uvv, uvv, uvv);

    if (parts >= 3) {
        // sequential per-lane noise keeps the live set small for the reg cap
        float4 nz;
        nz.x = threefry_noise((uint32_t)idx);
        nz.y = threefry_noise((uint32_t)idx + 1u);
        nz.z = threefry_noise((uint32_t)idx + 2u);
        nz.w = threefry_noise((uint32_t)idx + 3u);
        *reinterpret_cast<float4*>(out + 2*TOTAL + idx) = nz;
    }
}

// ---------------------------------------------------------------------------
extern "C" void kernel_launch(void* const* d_in, const int* in_sizes, int n_in,
                              void* d_out, int out_size) {
    const float* f0 = (const float*)d_in[0];
    const float* w  = (const float*)d_in[1];
    const float* b  = (const float*)d_in[2];
    float* out = (float*)d_out;
    int parts = out_size / TOTAL;   // 1: sine_merge, 2: +uv, 3: +noise

    prep_kernel<<<NROWS, 32>>>(f0);
    fused_kernel<<<dim3(TT, BB), 128>>>(f0, w, b, out, parts);
}